// round 3
// baseline (speedup 1.0000x reference)
#include <cuda_runtime.h>
#include <math.h>

// ---------------- f32x2 packed-math helpers ----------------
typedef unsigned long long ull;

#define FMA2(d, a, b) asm("fma.rn.f32x2 %0, %1, %2, %0;" : "+l"(d) : "l"(a), "l"(b))
#define MUL2(d, a, b) asm("mul.rn.f32x2 %0, %1, %2;" : "=l"(d) : "l"(a), "l"(b))

__device__ __forceinline__ ull dup2f(float a) {
    ull r; asm("mov.b64 %0, {%1, %1};" : "=l"(r) : "f"(a)); return r;
}
__device__ __forceinline__ float2 unpk(ull v) {
    float2 f; asm("mov.b64 {%0, %1}, %2;" : "=f"(f.x), "=f"(f.y) : "l"(v)); return f;
}

// ---------------- device scratch (no allocation allowed) ----------------
__device__ float g_pre[(size_t)16384 * 3072];   // [t*32+b][3072]: fwG(1024) fwC(512) bwG(1024) bwC(512)
__device__ float g_xt [(size_t)512 * 32 * 256]; // x transposed: [t][b][256]
__device__ float g_outf[(size_t)512 * 32 * 512];// fw hidden [t][b][512]
__device__ float g_outb[(size_t)512 * 32 * 512];// bw hidden [t][b][512]
__device__ float g_h  [2 * 32 * 512];           // current h [d][b][512]
__device__ float g_ru [2 * 32 * 1024];          // sigmoided gates [d][b][1024]
__device__ float g_pool[32 * 512];              // max-pool result
__device__ unsigned g_cnt2[2];
__device__ volatile unsigned g_gen2[2];

// ---------------- init ----------------
__global__ void k_init() {
    int i = blockIdx.x * blockDim.x + threadIdx.x;
    if (i < 2 * 32 * 512) g_h[i] = 0.f;
    if (i < 32 * 512)     g_pool[i] = 0.f;
    if (i < 2) { g_cnt2[i] = 0u; *(unsigned*)&g_gen2[i] = 0u; }
}

// ---------------- x -> [t][b][c] copy ----------------
__global__ void k_xcopy(const float* __restrict__ x) {
    int idx = blockIdx.x * blockDim.x + threadIdx.x;  // float4 id
    if (idx < 32 * 512 * 64) {
        int row = idx >> 6, c4 = idx & 63;            // row = b*512 + t
        int b = row >> 9, t = row & 511;
        ((float4*)g_xt)[(size_t)(t * 32 + b) * 64 + c4] = ((const float4*)x)[idx];
    }
}

// ---------------- GEMM1: x-part projections (M=16384,K=256,N=3072) ----------------
// 128x128 tile, 8x8 per thread, f32x2 packed inner loop.
__global__ __launch_bounds__(256, 2) void k_gemm_pre(
    const float* __restrict__ x,
    const float* __restrict__ fwWg, const float* __restrict__ fwbg,
    const float* __restrict__ fwWc, const float* __restrict__ fwbc,
    const float* __restrict__ bwWg, const float* __restrict__ bwbg,
    const float* __restrict__ bwWc, const float* __restrict__ bwbc)
{
    __shared__ __align__(16) float As[16 * 132];
    __shared__ __align__(16) float Bs[16 * 132];
    const int n0 = blockIdx.x * 128;
    const int m0 = blockIdx.y * 128;
    const float* W; const float* bias; int ld, nrel;
    if (n0 < 1024)      { W = fwWg; bias = fwbg; ld = 1024; nrel = n0; }
    else if (n0 < 1536) { W = fwWc; bias = fwbc; ld = 512;  nrel = n0 - 1024; }
    else if (n0 < 2560) { W = bwWg; bias = bwbg; ld = 1024; nrel = n0 - 1536; }
    else                { W = bwWc; bias = bwbc; ld = 512;  nrel = n0 - 2560; }
    const int tid = threadIdx.x;
    const int tx = tid & 15, ty = tid >> 4;
    ull acc[8][4];
#pragma unroll
    for (int i = 0; i < 8; i++)
#pragma unroll
        for (int j = 0; j < 4; j++) acc[i][j] = 0ull;

    for (int k0 = 0; k0 < 256; k0 += 16) {
#pragma unroll
        for (int i = 0; i < 2; ++i) {
            int f = tid + i * 256;
            int r = f >> 2, c4 = (f & 3) * 4;
            float4 v = *(const float4*)&x[(size_t)(m0 + r) * 256 + k0 + c4];
            As[(c4 + 0) * 132 + r] = v.x;
            As[(c4 + 1) * 132 + r] = v.y;
            As[(c4 + 2) * 132 + r] = v.z;
            As[(c4 + 3) * 132 + r] = v.w;
        }
#pragma unroll
        for (int i = 0; i < 2; ++i) {
            int f = tid + i * 256;
            int kk = f >> 5, n4 = (f & 31) * 4;
            *(float4*)&Bs[kk * 132 + n4] = *(const float4*)&W[(size_t)(k0 + kk) * ld + nrel + n4];
        }
        __syncthreads();
#pragma unroll
        for (int kk = 0; kk < 16; ++kk) {
            float4 a0 = *(const float4*)&As[kk * 132 + ty * 8];
            float4 a1 = *(const float4*)&As[kk * 132 + ty * 8 + 4];
            ulonglong2 w01 = *(const ulonglong2*)&Bs[kk * 132 + tx * 8];
            ulonglong2 w23 = *(const ulonglong2*)&Bs[kk * 132 + tx * 8 + 4];
            ull ad[8];
            ad[0] = dup2f(a0.x); ad[1] = dup2f(a0.y); ad[2] = dup2f(a0.z); ad[3] = dup2f(a0.w);
            ad[4] = dup2f(a1.x); ad[5] = dup2f(a1.y); ad[6] = dup2f(a1.z); ad[7] = dup2f(a1.w);
#pragma unroll
            for (int i = 0; i < 8; i++) {
                FMA2(acc[i][0], ad[i], w01.x);
                FMA2(acc[i][1], ad[i], w01.y);
                FMA2(acc[i][2], ad[i], w23.x);
                FMA2(acc[i][3], ad[i], w23.y);
            }
        }
        __syncthreads();
    }
    float4 bb0 = *(const float4*)&bias[nrel + tx * 8];
    float4 bb1 = *(const float4*)&bias[nrel + tx * 8 + 4];
    float bcol[8] = {bb0.x, bb0.y, bb0.z, bb0.w, bb1.x, bb1.y, bb1.z, bb1.w};
#pragma unroll
    for (int i = 0; i < 8; i++) {
        int m = m0 + ty * 8 + i;
        int trow = (m & 511) * 32 + (m >> 9);   // -> [t][b]
        float* orow = &g_pre[(size_t)trow * 3072 + n0 + tx * 8];
#pragma unroll
        for (int j = 0; j < 4; j++) {
            float2 v = unpk(acc[i][j]);
            v.x += bcol[2 * j]; v.y += bcol[2 * j + 1];
            *(float2*)&orow[2 * j] = v;
        }
    }
}

// ---------------- grid barrier (per direction, monotonic count) ----------------
__device__ __forceinline__ void gsync(int dir, unsigned target) {
    __syncthreads();
    if (threadIdx.x == 0) {
        __threadfence();
        unsigned arr = atomicAdd(&g_cnt2[dir], 1u) + 1u;
        if (arr == target * 64u) {
            atomicExch((unsigned*)&g_gen2[dir], target);
        } else {
            while (g_gen2[dir] < target) { }
        }
        __threadfence();
    }
    __syncthreads();
}

// ---------------- persistent bidirectional GRU ----------------
__global__ __launch_bounds__(256, 1) void k_recur(
    const float* __restrict__ fwWg, const float* __restrict__ fwWc,
    const float* __restrict__ bwWg, const float* __restrict__ bwWc)
{
    extern __shared__ float sm[];
    float* Wg_s = sm;             // 16 x 516
    float* Wc_s = sm + 8256;      // 8 x 516
    float* h_s  = sm + 12384;     // 32*512 floats, float4 XOR-swizzled [b][kc]
    float* red  = sm + 28768;     // 8 x 528 reduction buffer

    const int tid = threadIdx.x;
    const int cta = blockIdx.x;
    const int dir = cta >> 6;
    const int c64 = cta & 63;
    const int jg0 = c64 * 16;
    const int jc0 = c64 * 8;
    const float* Wg = dir ? bwWg : fwWg;
    const float* Wc = dir ? bwWc : fwWc;

    for (int idx = tid; idx < 16 * 512; idx += 256) {
        int jj = idx & 15, k = idx >> 4;
        Wg_s[jj * 516 + k] = Wg[(size_t)(256 + k) * 1024 + jg0 + jj];
    }
    for (int idx = tid; idx < 8 * 512; idx += 256) {
        int ii = idx & 7, k = idx >> 3;
        Wc_s[ii * 516 + k] = Wc[(size_t)(256 + k) * 512 + jc0 + ii];
    }

    const int warp = tid >> 5;
    const int b = tid & 31;
    const int kc0 = warp * 16;
    float4* h4p = (float4*)h_s;
    ulonglong2* h8 = (ulonglong2*)h_s;
    const float4* gh4 = (const float4*)g_h;
    const ulonglong2* wg8 = (const ulonglong2*)Wg_s;
    const ulonglong2* wc8 = (const ulonglong2*)Wc_s;
    unsigned bar = 0;

    for (int s = 0; s < 512; ++s) {
        const int t = dir ? (511 - s) : s;
        // ---- stage h into swizzled smem ----
        for (int f = tid; f < 4096; f += 256) {
            int bb = f >> 7, kc = f & 127;
            h4p[bb * 128 + (kc ^ (bb & 7))] = gh4[dir * 4096 + f];
        }
        __syncthreads();
        // ---- gate GEMM (packed): warp = k-slice, lanes = batch, 16 cols ----
        {
            ull acc[16];
#pragma unroll
            for (int jj = 0; jj < 16; ++jj) acc[jj] = 0ull;
#pragma unroll 4
            for (int kc = kc0; kc < kc0 + 16; ++kc) {
                ulonglong2 hh = h8[b * 128 + (kc ^ (b & 7))];
#pragma unroll
                for (int jj = 0; jj < 16; ++jj) {
                    ulonglong2 ww = wg8[jj * 129 + kc];
                    FMA2(acc[jj], hh.x, ww.x);
                    FMA2(acc[jj], hh.y, ww.y);
                }
            }
#pragma unroll
            for (int jj = 0; jj < 16; ++jj) {
                float2 v = unpk(acc[jj]);
                red[warp * 528 + jj * 33 + b] = v.x + v.y;
            }
        }
        __syncthreads();
        // ---- reduce + sigmoid -> g_ru ----
        for (int o = tid; o < 512; o += 256) {
            int jj = o & 15, bb = o >> 4;
            float v = 0.f;
#pragma unroll
            for (int q = 0; q < 8; ++q) v += red[q * 528 + jj * 33 + bb];
            v += g_pre[(size_t)(t * 32 + bb) * 3072 + (dir ? 1536 : 0) + jg0 + jj];
            g_ru[(dir * 32 + bb) * 1024 + jg0 + jj] = 1.f / (1.f + expf(-v));
        }
        gsync(dir, ++bar);
        // ---- phase B: candidate + update ----
        float hold;
        {
            int ii = tid & 7, bb = tid >> 3;
            int i = jc0 + ii;
            hold = h_s[(bb * 128 + ((i >> 2) ^ (bb & 7))) * 4 + (i & 3)];
        }
        __syncthreads();
        // rh = r * h, in place (packed)
        for (int f = tid; f < 4096; f += 256) {
            int bb = f >> 7, kc = f & 127;
            ulonglong2 r2 = *(const ulonglong2*)&g_ru[(dir * 32 + bb) * 1024 + kc * 4];
            int p = bb * 128 + (kc ^ (bb & 7));
            ulonglong2 h2 = h8[p];
            MUL2(h2.x, h2.x, r2.x);
            MUL2(h2.y, h2.y, r2.y);
            h8[p] = h2;
        }
        __syncthreads();
        // cand GEMM (packed): 8 cols
        {
            ull acc[8];
#pragma unroll
            for (int ii = 0; ii < 8; ++ii) acc[ii] = 0ull;
#pragma unroll 4
            for (int kc = kc0; kc < kc0 + 16; ++kc) {
                ulonglong2 hh = h8[b * 128 + (kc ^ (b & 7))];
#pragma unroll
                for (int ii = 0; ii < 8; ++ii) {
                    ulonglong2 ww = wc8[ii * 129 + kc];
                    FMA2(acc[ii], hh.x, ww.x);
                    FMA2(acc[ii], hh.y, ww.y);
                }
            }
#pragma unroll
            for (int ii = 0; ii < 8; ++ii) {
                float2 v = unpk(acc[ii]);
                red[warp * 264 + ii * 33 + b] = v.x + v.y;
            }
        }
        __syncthreads();
        {
            int ii = tid & 7, bb = tid >> 3;
            float v = 0.f;
#pragma unroll
            for (int q = 0; q < 8; ++q) v += red[q * 264 + ii * 33 + bb];
            v += g_pre[(size_t)(t * 32 + bb) * 3072 + (dir ? 2560 : 1024) + jc0 + ii];
            float ct = tanhf(v);
            float u = g_ru[(dir * 32 + bb) * 1024 + 512 + jc0 + ii];
            float hn = u * hold + (1.f - u) * ct;
            g_h[(dir * 32 + bb) * 512 + jc0 + ii] = hn;
            float* outp = dir ? g_outb : g_outf;
            outp[(size_t)(t * 32 + bb) * 512 + jc0 + ii] = hn;
        }
        gsync(dir, ++bar);
    }
}

// ---------------- FC over shifted-context concat + relu + max-pool ----------------
// M=16384 (t*32+b), N=512, K=1280. 128x128 tile, packed inner.
__global__ __launch_bounds__(256, 2) void k_fc(const float* __restrict__ fcw,
                                               const float* __restrict__ fcb)
{
    __shared__ __align__(16) float As[16 * 132];
    __shared__ __align__(16) float Bs[16 * 132];
    const int n0 = blockIdx.x * 128;
    const int m0 = blockIdx.y * 128;
    const int tid = threadIdx.x;
    const int tx = tid & 15, ty = tid >> 4;
    ull acc[8][4];
#pragma unroll
    for (int i = 0; i < 8; i++)
#pragma unroll
        for (int j = 0; j < 4; j++) acc[i][j] = 0ull;

    for (int k0 = 0; k0 < 1280; k0 += 16) {
#pragma unroll
        for (int i = 0; i < 2; ++i) {
            int f = tid + i * 256;
            int r = f >> 2, c4 = (f & 3) * 4;
            int m = m0 + r;
            int c = k0 + c4;
            float4 v = make_float4(0.f, 0.f, 0.f, 0.f);
            if (c < 512) {                        // c_left = out_fw[t-1]
                if (m >= 32) v = *(const float4*)&g_outf[(size_t)(m - 32) * 512 + c];
            } else if (c < 768) {                 // x[t]
                v = *(const float4*)&g_xt[(size_t)m * 256 + (c - 512)];
            } else {                              // c_right = out_bw[t+1]
                if (m < 16352) v = *(const float4*)&g_outb[(size_t)(m + 32) * 512 + (c - 768)];
            }
            As[(c4 + 0) * 132 + r] = v.x;
            As[(c4 + 1) * 132 + r] = v.y;
            As[(c4 + 2) * 132 + r] = v.z;
            As[(c4 + 3) * 132 + r] = v.w;
        }
#pragma unroll
        for (int i = 0; i < 2; ++i) {
            int f = tid + i * 256;
            int kk = f >> 5, n4 = (f & 31) * 4;
            *(float4*)&Bs[kk * 132 + n4] = *(const float4*)&fcw[(size_t)(k0 + kk) * 512 + n0 + n4];
        }
        __syncthreads();
#pragma unroll
        for (int kk = 0; kk < 16; ++kk) {
            float4 a0 = *(const float4*)&As[kk * 132 + ty * 8];
            float4 a1 = *(const float4*)&As[kk * 132 + ty * 8 + 4];
            ulonglong2 w01 = *(const ulonglong2*)&Bs[kk * 132 + tx * 8];
            ulonglong2 w23 = *(const ulonglong2*)&Bs[kk * 132 + tx * 8 + 4];
            ull ad[8];
            ad[0] = dup2f(a0.x); ad[1] = dup2f(a0.y); ad[2] = dup2f(a0.z); ad[3] = dup2f(a0.w);
            ad[4] = dup2f(a1.x); ad[5] = dup2f(a1.y); ad[6] = dup2f(a1.z); ad[7] = dup2f(a1.w);
#pragma unroll
            for (int i = 0; i < 8; i++) {
                FMA2(acc[i][0], ad[i], w01.x);
                FMA2(acc[i][1], ad[i], w01.y);
                FMA2(acc[i][2], ad[i], w23.x);
                FMA2(acc[i][3], ad[i], w23.y);
            }
        }
        __syncthreads();
    }
    float4 bb0 = *(const float4*)&fcb[n0 + tx * 8];
    float4 bb1 = *(const float4*)&fcb[n0 + tx * 8 + 4];
    float bcol[8] = {bb0.x, bb0.y, bb0.z, bb0.w, bb1.x, bb1.y, bb1.z, bb1.w};
#pragma unroll
    for (int i = 0; i < 8; i++) {
        int m = m0 + ty * 8 + i;
        int bb = m & 31;
        int base = bb * 512 + n0 + tx * 8;
#pragma unroll
        for (int j = 0; j < 4; j++) {
            float2 v = unpk(acc[i][j]);
            float r0 = fmaxf(v.x + bcol[2 * j], 0.f);
            float r1 = fmaxf(v.y + bcol[2 * j + 1], 0.f);
            atomicMax((int*)&g_pool[base + 2 * j + 0], __float_as_int(r0));
            atomicMax((int*)&g_pool[base + 2 * j + 1], __float_as_int(r1));
        }
    }
}

// ---------------- MLP head ----------------
__global__ void k_mlp(const float* __restrict__ mw, const float* __restrict__ mb,
                      float* __restrict__ out)
{
    __shared__ float sp[512];
    int bb = blockIdx.x;
    int tid = threadIdx.x;
    for (int i = tid; i < 512; i += 256) sp[i] = g_pool[bb * 512 + i];
    __syncthreads();
    float acc = mb[tid];
#pragma unroll 8
    for (int h = 0; h < 512; ++h) acc += sp[h] * mw[h * 256 + tid];
    out[bb * 256 + tid] = acc;
}

// ---------------- launch ----------------
extern "C" void kernel_launch(void* const* d_in, const int* in_sizes, int n_in,
                              void* d_out, int out_size)
{
    const float* x    = (const float*)d_in[0];
    const float* fwWg = (const float*)d_in[1];
    const float* fwbg = (const float*)d_in[2];
    const float* fwWc = (const float*)d_in[3];
    const float* fwbc = (const float*)d_in[4];
    const float* bwWg = (const float*)d_in[5];
    const float* bwbg = (const float*)d_in[6];
    const float* bwWc = (const float*)d_in[7];
    const float* bwbc = (const float*)d_in[8];
    const float* fcw  = (const float*)d_in[9];
    const float* fcb  = (const float*)d_in[10];
    const float* mw   = (const float*)d_in[11];
    const float* mb   = (const float*)d_in[12];
    float* out = (float*)d_out;

    cudaFuncSetAttribute(k_recur, cudaFuncAttributeMaxDynamicSharedMemorySize, 131968);

    k_init<<<128, 256>>>();
    k_xcopy<<<4096, 256>>>(x);
    k_gemm_pre<<<dim3(24, 128), 256>>>(x, fwWg, fwbg, fwWc, fwbc, bwWg, bwbg, bwWc, bwbc);
    k_recur<<<128, 256, 131968>>>(fwWg, fwWc, bwWg, bwWc);
    k_fc<<<dim3(4, 128), 256>>>(fcw, fcb);
    k_mlp<<<32, 256>>>(mw, mb, out);
}

// round 4
// speedup vs baseline: 1.1830x; 1.1830x over previous
#include <cuda_runtime.h>
#include <math.h>

typedef unsigned long long ull;

#define FMA2(d, a, b) asm("fma.rn.f32x2 %0, %1, %2, %0;" : "+l"(d) : "l"(a), "l"(b))
#define MUL2(d, a, b) asm("mul.rn.f32x2 %0, %1, %2;" : "=l"(d) : "l"(a), "l"(b))
#define PACK2(d, lo, hi) asm("mov.b64 %0, {%1, %2};" : "=l"(d) : "f"(lo), "f"(hi))

__device__ __forceinline__ ull dup2f(float a) {
    ull r; asm("mov.b64 %0, {%1, %1};" : "=l"(r) : "f"(a)); return r;
}
__device__ __forceinline__ float2 unpk(ull v) {
    float2 f; asm("mov.b64 {%0, %1}, %2;" : "=f"(f.x), "=f"(f.y) : "l"(v)); return f;
}

// ---------------- device scratch ----------------
// x-projections, CTA-sliced layouts: [dir*64+c64][t][sub][b]
__device__ float g_preG[(size_t)2 * 64 * 512 * 16 * 32];
__device__ float g_preC[(size_t)2 * 64 * 512 * 8 * 32];
__device__ float g_xt [(size_t)512 * 32 * 256];  // x: [t][b][c]
__device__ float g_outf[(size_t)512 * 32 * 512]; // fw hidden [t][b][h]
__device__ float g_outb[(size_t)512 * 32 * 512]; // bw hidden [t][b][h]
__device__ float g_hT [2 * 512 * 32];            // h transposed [dir][col][b]
__device__ float g_ruT[2 * 1024 * 32];           // gates transposed [dir][col][b]
__device__ float g_pool[32 * 512];
__device__ unsigned g_cnt2[2];
__device__ volatile unsigned g_gen2[2];

// ---------------- init ----------------
__global__ void k_init() {
    int i = blockIdx.x * blockDim.x + threadIdx.x;
    if (i < 2 * 512 * 32) g_hT[i] = 0.f;
    if (i < 32 * 512)     g_pool[i] = 0.f;
    if (i < 2) { g_cnt2[i] = 0u; *(unsigned*)&g_gen2[i] = 0u; }
}

// ---------------- x -> [t][b][c] copy ----------------
__global__ void k_xcopy(const float* __restrict__ x) {
    int idx = blockIdx.x * blockDim.x + threadIdx.x;  // float4 id
    if (idx < 32 * 512 * 64) {
        int row = idx >> 6, c4 = idx & 63;            // row = b*512 + t
        int b = row >> 9, t = row & 511;
        ((float4*)g_xt)[(size_t)(t * 32 + b) * 64 + c4] = ((const float4*)x)[idx];
    }
}

// ---------------- GEMM1: x-part projections (M=16384,K=256,N=3072) ----------------
__global__ __launch_bounds__(256, 2) void k_gemm_pre(
    const float* __restrict__ x,
    const float* __restrict__ fwWg, const float* __restrict__ fwbg,
    const float* __restrict__ fwWc, const float* __restrict__ fwbc,
    const float* __restrict__ bwWg, const float* __restrict__ bwbg,
    const float* __restrict__ bwWc, const float* __restrict__ bwbc)
{
    __shared__ __align__(16) float As[16 * 132];
    __shared__ __align__(16) float Bs[16 * 132];
    const int n0 = blockIdx.x * 128;
    const int m0 = blockIdx.y * 128;
    const float* W; const float* bias; int ld, nrel, dir, isC;
    if (n0 < 1024)      { W = fwWg; bias = fwbg; ld = 1024; nrel = n0;        dir = 0; isC = 0; }
    else if (n0 < 1536) { W = fwWc; bias = fwbc; ld = 512;  nrel = n0 - 1024; dir = 0; isC = 1; }
    else if (n0 < 2560) { W = bwWg; bias = bwbg; ld = 1024; nrel = n0 - 1536; dir = 1; isC = 0; }
    else                { W = bwWc; bias = bwbc; ld = 512;  nrel = n0 - 2560; dir = 1; isC = 1; }
    const int tid = threadIdx.x;
    const int tx = tid & 15, ty = tid >> 4;
    ull acc[8][4];
#pragma unroll
    for (int i = 0; i < 8; i++)
#pragma unroll
        for (int j = 0; j < 4; j++) acc[i][j] = 0ull;

    for (int k0 = 0; k0 < 256; k0 += 16) {
#pragma unroll
        for (int i = 0; i < 2; ++i) {
            int f = tid + i * 256;
            int r = f >> 2, c4 = (f & 3) * 4;
            float4 v = *(const float4*)&x[(size_t)(m0 + r) * 256 + k0 + c4];
            As[(c4 + 0) * 132 + r] = v.x;
            As[(c4 + 1) * 132 + r] = v.y;
            As[(c4 + 2) * 132 + r] = v.z;
            As[(c4 + 3) * 132 + r] = v.w;
        }
#pragma unroll
        for (int i = 0; i < 2; ++i) {
            int f = tid + i * 256;
            int kk = f >> 5, n4 = (f & 31) * 4;
            *(float4*)&Bs[kk * 132 + n4] = *(const float4*)&W[(size_t)(k0 + kk) * ld + nrel + n4];
        }
        __syncthreads();
#pragma unroll
        for (int kk = 0; kk < 16; ++kk) {
            float4 a0 = *(const float4*)&As[kk * 132 + ty * 8];
            float4 a1 = *(const float4*)&As[kk * 132 + ty * 8 + 4];
            ulonglong2 w01 = *(const ulonglong2*)&Bs[kk * 132 + tx * 8];
            ulonglong2 w23 = *(const ulonglong2*)&Bs[kk * 132 + tx * 8 + 4];
            ull ad[8];
            ad[0] = dup2f(a0.x); ad[1] = dup2f(a0.y); ad[2] = dup2f(a0.z); ad[3] = dup2f(a0.w);
            ad[4] = dup2f(a1.x); ad[5] = dup2f(a1.y); ad[6] = dup2f(a1.z); ad[7] = dup2f(a1.w);
#pragma unroll
            for (int i = 0; i < 8; i++) {
                FMA2(acc[i][0], ad[i], w01.x);
                FMA2(acc[i][1], ad[i], w01.y);
                FMA2(acc[i][2], ad[i], w23.x);
                FMA2(acc[i][3], ad[i], w23.y);
            }
        }
        __syncthreads();
    }
    float4 bb0 = *(const float4*)&bias[nrel + tx * 8];
    float4 bb1 = *(const float4*)&bias[nrel + tx * 8 + 4];
    float bcol[8] = {bb0.x, bb0.y, bb0.z, bb0.w, bb1.x, bb1.y, bb1.z, bb1.w};
    const int cbase = nrel + tx * 8;
#pragma unroll
    for (int i = 0; i < 8; i++) {
        int m = m0 + ty * 8 + i;
        int t = m & 511, bb = m >> 9;
        float vals[8];
#pragma unroll
        for (int j = 0; j < 4; j++) {
            float2 v = unpk(acc[i][j]);
            vals[2 * j] = v.x + bcol[2 * j];
            vals[2 * j + 1] = v.y + bcol[2 * j + 1];
        }
        if (!isC) {
            int c64b = cbase >> 4, jjb = cbase & 15;
            float* dst = &g_preG[(((size_t)(dir * 64 + c64b) * 512 + t) * 16 + jjb) * 32 + bb];
#pragma unroll
            for (int cc = 0; cc < 8; ++cc) dst[cc * 32] = vals[cc];
        } else {
            int c64b = cbase >> 3;
            float* dst = &g_preC[(((size_t)(dir * 64 + c64b) * 512 + t) * 8) * 32 + bb];
#pragma unroll
            for (int cc = 0; cc < 8; ++cc) dst[cc * 32] = vals[cc];
        }
    }
}

// ---------------- grid barrier (per direction, monotonic count) ----------------
__device__ __forceinline__ void gsync(int dir, unsigned target) {
    __syncthreads();
    if (threadIdx.x == 0) {
        __threadfence();
        unsigned arr = atomicAdd(&g_cnt2[dir], 1u) + 1u;
        if (arr == target * 64u) {
            atomicExch((unsigned*)&g_gen2[dir], target);
        } else {
            while (g_gen2[dir] < target) { }
        }
        __threadfence();
    }
    __syncthreads();
}

// ---------------- persistent bidirectional GRU ----------------
// 128 CTAs: dir = cta>>6; each CTA owns 16 gate cols + 8 cand cols (weights pinned in smem).
// h, r, rh live in registers (warp = 64-wide k-slice, lane = batch).
__global__ __launch_bounds__(256, 1) void k_recur(
    const float* __restrict__ fwWg, const float* __restrict__ fwWc,
    const float* __restrict__ bwWg, const float* __restrict__ bwWc)
{
    extern __shared__ float sm[];
    float* Wg_s = sm;           // 16 x 516
    float* Wc_s = sm + 8256;    // 8 x 516
    float* red  = sm + 12384;   // 8 x 528

    const int tid = threadIdx.x;
    const int cta = blockIdx.x;
    const int dir = cta >> 6;
    const int c64 = cta & 63;
    const int jg0 = c64 * 16;
    const int jc0 = c64 * 8;
    const float* Wg = dir ? bwWg : fwWg;
    const float* Wc = dir ? bwWc : fwWc;

    for (int idx = tid; idx < 16 * 512; idx += 256) {
        int jj = idx & 15, k = idx >> 4;
        Wg_s[jj * 516 + k] = Wg[(size_t)(256 + k) * 1024 + jg0 + jj];
    }
    for (int idx = tid; idx < 8 * 512; idx += 256) {
        int ii = idx & 7, k = idx >> 3;
        Wc_s[ii * 516 + k] = Wc[(size_t)(256 + k) * 512 + jc0 + ii];
    }
    __syncthreads();

    const int warp = tid >> 5;
    const int b = tid & 31;
    const int k0 = warp * 64;
    const int rjj = tid >> 5;   // reduce mapping: jj and jj+8
    const int rbb = tid & 31;
    const int eii = tid >> 5;   // epilogue mapping: 8 cand cols x 32 b
    const int ebb = tid & 31;

    const float* preG = g_preG + (size_t)(dir * 64 + c64) * 512 * 16 * 32;
    const float* preC = g_preC + (size_t)(dir * 64 + c64) * 512 * 8 * 32;
    float* ruT = g_ruT + (size_t)dir * 1024 * 32;
    float* hT  = g_hT  + (size_t)dir * 512 * 32;
    float* outp = dir ? g_outb : g_outf;

    unsigned bar = 0;
    // prefetch step-0 x-projections
    float pgA, pgB, pcA;
    {
        int t = dir ? 511 : 0;
        pgA = preG[((size_t)t * 16 + rjj) * 32 + rbb];
        pgB = preG[((size_t)t * 16 + rjj + 8) * 32 + rbb];
        pcA = preC[((size_t)t * 8 + eii) * 32 + ebb];
    }

    for (int s = 0; s < 512; ++s) {
        const int t  = dir ? (511 - s) : s;
        const int tn = dir ? (510 - s) : (s + 1);

        // ---- load h slice + hold into registers (coalesced) ----
        float hr[64];
#pragma unroll
        for (int kk = 0; kk < 64; ++kk)
            hr[kk] = hT[(k0 + kk) * 32 + b];
        float hold = hT[(jc0 + eii) * 32 + ebb];
        ull hh[32];
#pragma unroll
        for (int q = 0; q < 32; ++q)
            PACK2(hh[q], hr[2 * q], hr[2 * q + 1]);

        // ---- gate GEMM: reg-h x smem-broadcast W ----
        ull acc[16];
#pragma unroll
        for (int jj = 0; jj < 16; ++jj) acc[jj] = 0ull;
#pragma unroll
        for (int q2 = 0; q2 < 16; ++q2) {
#pragma unroll
            for (int jj = 0; jj < 16; ++jj) {
                ulonglong2 ww = *(const ulonglong2*)&Wg_s[jj * 516 + k0 + q2 * 4];
                FMA2(acc[jj], hh[2 * q2],     ww.x);
                FMA2(acc[jj], hh[2 * q2 + 1], ww.y);
            }
        }
#pragma unroll
        for (int jj = 0; jj < 16; ++jj) {
            float2 v = unpk(acc[jj]);
            red[warp * 528 + jj * 33 + b] = v.x + v.y;
        }
        __syncthreads();

        // ---- reduce + sigmoid -> g_ruT (coalesced) ----
        {
            float v0 = pgA, v1 = pgB;
#pragma unroll
            for (int q = 0; q < 8; ++q) {
                v0 += red[q * 528 + rjj * 33 + rbb];
                v1 += red[q * 528 + (rjj + 8) * 33 + rbb];
            }
            ruT[(jg0 + rjj) * 32 + rbb]     = 1.f / (1.f + __expf(-v0));
            ruT[(jg0 + rjj + 8) * 32 + rbb] = 1.f / (1.f + __expf(-v1));
        }
        // prefetch next-step gate pre before the barrier
        if (s < 511) {
            pgA = preG[((size_t)tn * 16 + rjj) * 32 + rbb];
            pgB = preG[((size_t)tn * 16 + rjj + 8) * 32 + rbb];
        }
        gsync(dir, ++bar);

        // ---- load r + u, rh in registers ----
        float u = ruT[(512 + jc0 + eii) * 32 + ebb];
        float rr[64];
#pragma unroll
        for (int kk = 0; kk < 64; ++kk)
            rr[kk] = ruT[(k0 + kk) * 32 + b];
#pragma unroll
        for (int q = 0; q < 32; ++q) {
            ull rp;
            PACK2(rp, rr[2 * q], rr[2 * q + 1]);
            MUL2(hh[q], hh[q], rp);
        }

        // ---- cand GEMM ----
        ull acc2[8];
#pragma unroll
        for (int ii = 0; ii < 8; ++ii) acc2[ii] = 0ull;
#pragma unroll
        for (int q2 = 0; q2 < 16; ++q2) {
#pragma unroll
            for (int ii = 0; ii < 8; ++ii) {
                ulonglong2 ww = *(const ulonglong2*)&Wc_s[ii * 516 + k0 + q2 * 4];
                FMA2(acc2[ii], hh[2 * q2],     ww.x);
                FMA2(acc2[ii], hh[2 * q2 + 1], ww.y);
            }
        }
#pragma unroll
        for (int ii = 0; ii < 8; ++ii) {
            float2 v = unpk(acc2[ii]);
            red[warp * 264 + ii * 33 + b] = v.x + v.y;
        }
        __syncthreads();

        // ---- epilogue: tanh + h update ----
        {
            float v = pcA;
#pragma unroll
            for (int q = 0; q < 8; ++q) v += red[q * 264 + eii * 33 + ebb];
            float ct = tanhf(v);
            float hn = u * hold + (1.f - u) * ct;
            hT[(jc0 + eii) * 32 + ebb] = hn;
            outp[(size_t)(t * 32 + ebb) * 512 + jc0 + eii] = hn;
        }
        if (s < 511)
            pcA = preC[((size_t)tn * 8 + eii) * 32 + ebb];
        gsync(dir, ++bar);
    }
}

// ---------------- FC over shifted-context concat + relu + max-pool ----------------
__global__ __launch_bounds__(256, 2) void k_fc(const float* __restrict__ fcw,
                                               const float* __restrict__ fcb)
{
    __shared__ __align__(16) float As[16 * 132];
    __shared__ __align__(16) float Bs[16 * 132];
    const int n0 = blockIdx.x * 128;
    const int m0 = blockIdx.y * 128;
    const int tid = threadIdx.x;
    const int tx = tid & 15, ty = tid >> 4;
    ull acc[8][4];
#pragma unroll
    for (int i = 0; i < 8; i++)
#pragma unroll
        for (int j = 0; j < 4; j++) acc[i][j] = 0ull;

    for (int k0 = 0; k0 < 1280; k0 += 16) {
#pragma unroll
        for (int i = 0; i < 2; ++i) {
            int f = tid + i * 256;
            int r = f >> 2, c4 = (f & 3) * 4;
            int m = m0 + r;
            int c = k0 + c4;
            float4 v = make_float4(0.f, 0.f, 0.f, 0.f);
            if (c < 512) {                        // c_left = out_fw[t-1]
                if (m >= 32) v = *(const float4*)&g_outf[(size_t)(m - 32) * 512 + c];
            } else if (c < 768) {                 // x[t]
                v = *(const float4*)&g_xt[(size_t)m * 256 + (c - 512)];
            } else {                              // c_right = out_bw[t+1]
                if (m < 16352) v = *(const float4*)&g_outb[(size_t)(m + 32) * 512 + (c - 768)];
            }
            As[(c4 + 0) * 132 + r] = v.x;
            As[(c4 + 1) * 132 + r] = v.y;
            As[(c4 + 2) * 132 + r] = v.z;
            As[(c4 + 3) * 132 + r] = v.w;
        }
#pragma unroll
        for (int i = 0; i < 2; ++i) {
            int f = tid + i * 256;
            int kk = f >> 5, n4 = (f & 31) * 4;
            *(float4*)&Bs[kk * 132 + n4] = *(const float4*)&fcw[(size_t)(k0 + kk) * 512 + n0 + n4];
        }
        __syncthreads();
#pragma unroll
        for (int kk = 0; kk < 16; ++kk) {
            float4 a0 = *(const float4*)&As[kk * 132 + ty * 8];
            float4 a1 = *(const float4*)&As[kk * 132 + ty * 8 + 4];
            ulonglong2 w01 = *(const ulonglong2*)&Bs[kk * 132 + tx * 8];
            ulonglong2 w23 = *(const ulonglong2*)&Bs[kk * 132 + tx * 8 + 4];
            ull ad[8];
            ad[0] = dup2f(a0.x); ad[1] = dup2f(a0.y); ad[2] = dup2f(a0.z); ad[3] = dup2f(a0.w);
            ad[4] = dup2f(a1.x); ad[5] = dup2f(a1.y); ad[6] = dup2f(a1.z); ad[7] = dup2f(a1.w);
#pragma unroll
            for (int i = 0; i < 8; i++) {
                FMA2(acc[i][0], ad[i], w01.x);
                FMA2(acc[i][1], ad[i], w01.y);
                FMA2(acc[i][2], ad[i], w23.x);
                FMA2(acc[i][3], ad[i], w23.y);
            }
        }
        __syncthreads();
    }
    float4 bb0 = *(const float4*)&fcb[n0 + tx * 8];
    float4 bb1 = *(const float4*)&fcb[n0 + tx * 8 + 4];
    float bcol[8] = {bb0.x, bb0.y, bb0.z, bb0.w, bb1.x, bb1.y, bb1.z, bb1.w};
#pragma unroll
    for (int i = 0; i < 8; i++) {
        int m = m0 + ty * 8 + i;
        int bb = m & 31;
        int base = bb * 512 + n0 + tx * 8;
#pragma unroll
        for (int j = 0; j < 4; j++) {
            float2 v = unpk(acc[i][j]);
            float r0 = fmaxf(v.x + bcol[2 * j], 0.f);
            float r1 = fmaxf(v.y + bcol[2 * j + 1], 0.f);
            atomicMax((int*)&g_pool[base + 2 * j + 0], __float_as_int(r0));
            atomicMax((int*)&g_pool[base + 2 * j + 1], __float_as_int(r1));
        }
    }
}

// ---------------- MLP head ----------------
__global__ void k_mlp(const float* __restrict__ mw, const float* __restrict__ mb,
                      float* __restrict__ out)
{
    __shared__ float sp[512];
    int bb = blockIdx.x;
    int tid = threadIdx.x;
    for (int i = tid; i < 512; i += 256) sp[i] = g_pool[bb * 512 + i];
    __syncthreads();
    float acc = mb[tid];
#pragma unroll 8
    for (int h = 0; h < 512; ++h) acc += sp[h] * mw[h * 256 + tid];
    out[bb * 256 + tid] = acc;
}

// ---------------- launch ----------------
extern "C" void kernel_launch(void* const* d_in, const int* in_sizes, int n_in,
                              void* d_out, int out_size)
{
    const float* x    = (const float*)d_in[0];
    const float* fwWg = (const float*)d_in[1];
    const float* fwbg = (const float*)d_in[2];
    const float* fwWc = (const float*)d_in[3];
    const float* fwbc = (const float*)d_in[4];
    const float* bwWg = (const float*)d_in[5];
    const float* bwbg = (const float*)d_in[6];
    const float* bwWc = (const float*)d_in[7];
    const float* bwbc = (const float*)d_in[8];
    const float* fcw  = (const float*)d_in[9];
    const float* fcb  = (const float*)d_in[10];
    const float* mw   = (const float*)d_in[11];
    const float* mb   = (const float*)d_in[12];
    float* out = (float*)d_out;

    cudaFuncSetAttribute(k_recur, cudaFuncAttributeMaxDynamicSharedMemorySize, 67000);

    k_init<<<128, 256>>>();
    k_xcopy<<<4096, 256>>>(x);
    k_gemm_pre<<<dim3(24, 128), 256>>>(x, fwWg, fwbg, fwWc, fwbc, bwWg, bwbg, bwWc, bwbc);
    k_recur<<<128, 256, 67000>>>(fwWg, fwWc, bwWg, bwWc);
    k_fc<<<dim3(4, 128), 256>>>(fcw, fcb);
    k_mlp<<<32, 256>>>(mw, mb, out);
}

// round 5
// speedup vs baseline: 1.2808x; 1.0827x over previous
#include <cuda_runtime.h>
#include <math.h>

typedef unsigned long long ull;

#define FMA2(d, a, b) asm("fma.rn.f32x2 %0, %1, %2, %0;" : "+l"(d) : "l"(a), "l"(b))
#define MUL2(d, a, b) asm("mul.rn.f32x2 %0, %1, %2;" : "=l"(d) : "l"(a), "l"(b))
#define PACK2(d, lo, hi) asm("mov.b64 %0, {%1, %2};" : "=l"(d) : "f"(lo), "f"(hi))

__device__ __forceinline__ ull dup2f(float a) {
    ull r; asm("mov.b64 %0, {%1, %1};" : "=l"(r) : "f"(a)); return r;
}
__device__ __forceinline__ float2 unpk(ull v) {
    float2 f; asm("mov.b64 {%0, %1}, %2;" : "=f"(f.x), "=f"(f.y) : "l"(v)); return f;
}

// ---------------- device scratch ----------------
// gate pre [dir*64+c64][t][16][32] : sub 0..7 = r cols (c64*8+j), 8..15 = u cols (512+c64*8+j)
__device__ float g_preG[(size_t)2 * 64 * 512 * 16 * 32];
// cand pre [dir*64+c64][t][8][32]
__device__ float g_preC[(size_t)2 * 64 * 512 * 8 * 32];
__device__ float g_xt [(size_t)512 * 32 * 256];  // x: [t][b][c]
__device__ float g_outf[(size_t)512 * 32 * 512]; // fw hidden [t][b][h]
__device__ float g_outb[(size_t)512 * 32 * 512]; // bw hidden [t][b][h]
__device__ float g_hT [2 * 512 * 32];            // h transposed [dir][col][b]
__device__ float g_ruT[2 * 512 * 32];            // sigmoided r only [dir][col][b]
__device__ float g_pool[32 * 512];
__device__ unsigned g_cntA[2];
__device__ unsigned g_cntB[2];

// ---------------- init ----------------
__global__ void k_init() {
    int i = blockIdx.x * blockDim.x + threadIdx.x;
    if (i < 2 * 512 * 32) g_hT[i] = 0.f;
    if (i < 32 * 512)     g_pool[i] = 0.f;
    if (i < 2) { g_cntA[i] = 0u; g_cntB[i] = 0u; }
}

// ---------------- x -> [t][b][c] copy ----------------
__global__ void k_xcopy(const float* __restrict__ x) {
    int idx = blockIdx.x * blockDim.x + threadIdx.x;  // float4 id
    if (idx < 32 * 512 * 64) {
        int row = idx >> 6, c4 = idx & 63;            // row = b*512 + t
        int b = row >> 9, t = row & 511;
        ((float4*)g_xt)[(size_t)(t * 32 + b) * 64 + c4] = ((const float4*)x)[idx];
    }
}

// ---------------- GEMM1: x-part projections (M=16384,K=256,N=3072) ----------------
__global__ __launch_bounds__(256, 2) void k_gemm_pre(
    const float* __restrict__ x,
    const float* __restrict__ fwWg, const float* __restrict__ fwbg,
    const float* __restrict__ fwWc, const float* __restrict__ fwbc,
    const float* __restrict__ bwWg, const float* __restrict__ bwbg,
    const float* __restrict__ bwWc, const float* __restrict__ bwbc)
{
    __shared__ __align__(16) float As[16 * 132];
    __shared__ __align__(16) float Bs[16 * 132];
    const int n0 = blockIdx.x * 128;
    const int m0 = blockIdx.y * 128;
    const float* W; const float* bias; int ld, nrel, dir, isC;
    if (n0 < 1024)      { W = fwWg; bias = fwbg; ld = 1024; nrel = n0;        dir = 0; isC = 0; }
    else if (n0 < 1536) { W = fwWc; bias = fwbc; ld = 512;  nrel = n0 - 1024; dir = 0; isC = 1; }
    else if (n0 < 2560) { W = bwWg; bias = bwbg; ld = 1024; nrel = n0 - 1536; dir = 1; isC = 0; }
    else                { W = bwWc; bias = bwbc; ld = 512;  nrel = n0 - 2560; dir = 1; isC = 1; }
    const int tid = threadIdx.x;
    const int tx = tid & 15, ty = tid >> 4;
    ull acc[8][4];
#pragma unroll
    for (int i = 0; i < 8; i++)
#pragma unroll
        for (int j = 0; j < 4; j++) acc[i][j] = 0ull;

    for (int k0 = 0; k0 < 256; k0 += 16) {
#pragma unroll
        for (int i = 0; i < 2; ++i) {
            int f = tid + i * 256;
            int r = f >> 2, c4 = (f & 3) * 4;
            float4 v = *(const float4*)&x[(size_t)(m0 + r) * 256 + k0 + c4];
            As[(c4 + 0) * 132 + r] = v.x;
            As[(c4 + 1) * 132 + r] = v.y;
            As[(c4 + 2) * 132 + r] = v.z;
            As[(c4 + 3) * 132 + r] = v.w;
        }
#pragma unroll
        for (int i = 0; i < 2; ++i) {
            int f = tid + i * 256;
            int kk = f >> 5, n4 = (f & 31) * 4;
            *(float4*)&Bs[kk * 132 + n4] = *(const float4*)&W[(size_t)(k0 + kk) * ld + nrel + n4];
        }
        __syncthreads();
#pragma unroll
        for (int kk = 0; kk < 16; ++kk) {
            float4 a0 = *(const float4*)&As[kk * 132 + ty * 8];
            float4 a1 = *(const float4*)&As[kk * 132 + ty * 8 + 4];
            ulonglong2 w01 = *(const ulonglong2*)&Bs[kk * 132 + tx * 8];
            ulonglong2 w23 = *(const ulonglong2*)&Bs[kk * 132 + tx * 8 + 4];
            ull ad[8];
            ad[0] = dup2f(a0.x); ad[1] = dup2f(a0.y); ad[2] = dup2f(a0.z); ad[3] = dup2f(a0.w);
            ad[4] = dup2f(a1.x); ad[5] = dup2f(a1.y); ad[6] = dup2f(a1.z); ad[7] = dup2f(a1.w);
#pragma unroll
            for (int i = 0; i < 8; i++) {
                FMA2(acc[i][0], ad[i], w01.x);
                FMA2(acc[i][1], ad[i], w01.y);
                FMA2(acc[i][2], ad[i], w23.x);
                FMA2(acc[i][3], ad[i], w23.y);
            }
        }
        __syncthreads();
    }
    float4 bb0 = *(const float4*)&bias[nrel + tx * 8];
    float4 bb1 = *(const float4*)&bias[nrel + tx * 8 + 4];
    float bcol[8] = {bb0.x, bb0.y, bb0.z, bb0.w, bb1.x, bb1.y, bb1.z, bb1.w};
    const int cbase = nrel + tx * 8;
#pragma unroll
    for (int i = 0; i < 8; i++) {
        int m = m0 + ty * 8 + i;
        int t = m & 511, bb = m >> 9;
        float vals[8];
#pragma unroll
        for (int j = 0; j < 4; j++) {
            float2 v = unpk(acc[i][j]);
            vals[2 * j] = v.x + bcol[2 * j];
            vals[2 * j + 1] = v.y + bcol[2 * j + 1];
        }
        if (!isC) {
            int c, sub0;
            if (cbase < 512) { c = cbase >> 3; sub0 = 0; }
            else             { c = (cbase - 512) >> 3; sub0 = 8; }
            float* dst = &g_preG[(((size_t)(dir * 64 + c) * 512 + t) * 16 + sub0) * 32 + bb];
#pragma unroll
            for (int cc = 0; cc < 8; ++cc) dst[cc * 32] = vals[cc];
        } else {
            int c = cbase >> 3;
            float* dst = &g_preC[(((size_t)(dir * 64 + c) * 512 + t) * 8) * 32 + bb];
#pragma unroll
            for (int cc = 0; cc < 8; ++cc) dst[cc * 32] = vals[cc];
        }
    }
}

// ---------------- split arrive / wait (per-direction monotonic counters) ----------------
__device__ __forceinline__ void arrive(unsigned* cnt) {
    __syncthreads();
    if (threadIdx.x == 0) {
        __threadfence();
        atomicAdd(cnt, 1u);
    }
}
__device__ __forceinline__ void wait_for(unsigned* cnt, unsigned target) {
    if (threadIdx.x == 0) {
        while (*(volatile unsigned*)cnt < target) { }
        __threadfence();
    }
    __syncthreads();
}

// ---------------- persistent bidirectional GRU ----------------
// 128 CTAs: dir = cta>>6, c64 = cta&63. Each CTA owns 8 r cols, 8 u cols, 8 cand cols
// (all = [c64*8, c64*8+8)). u never leaves registers. One hidden barrier (A), one exposed (B).
__global__ __launch_bounds__(256, 1) void k_recur(
    const float* __restrict__ fwWg, const float* __restrict__ fwWc,
    const float* __restrict__ bwWg, const float* __restrict__ bwWc)
{
    extern __shared__ float sm[];
    float* Wr_s = sm;             // 8 x 516
    float* Wu_s = sm + 4128;      // 8 x 516
    float* Wc_s = sm + 8256;      // 8 x 516
    float* red  = sm + 12384;     // 8 warps x 8 cols x 33

    const int tid = threadIdx.x;
    const int cta = blockIdx.x;
    const int dir = cta >> 6;
    const int c64 = cta & 63;
    const int j0 = c64 * 8;
    const float* Wg = dir ? bwWg : fwWg;
    const float* Wc = dir ? bwWc : fwWc;

    for (int idx = tid; idx < 8 * 512; idx += 256) {
        int jj = idx & 7, k = idx >> 3;
        Wr_s[jj * 516 + k] = Wg[(size_t)(256 + k) * 1024 + j0 + jj];
        Wu_s[jj * 516 + k] = Wg[(size_t)(256 + k) * 1024 + 512 + j0 + jj];
        Wc_s[jj * 516 + k] = Wc[(size_t)(256 + k) * 512 + j0 + jj];
    }
    __syncthreads();

    const int warp = tid >> 5;
    const int b = tid & 31;
    const int k0 = warp * 64;
    const int col = tid >> 5;    // reduce/epilogue mapping: 8 cols x 32 batch
    const int eb = tid & 31;

    const float* preG = g_preG + (size_t)(dir * 64 + c64) * 512 * 16 * 32;
    const float* preC = g_preC + (size_t)(dir * 64 + c64) * 512 * 8 * 32;
    float* ruT = g_ruT + (size_t)dir * 512 * 32;
    float* hT  = g_hT  + (size_t)dir * 512 * 32;
    float* outp = dir ? g_outb : g_outf;
    unsigned* cA = &g_cntA[dir];
    unsigned* cB = &g_cntB[dir];

    // prefetch step-0 x-projections
    float pgR, pgU, pcA;
    {
        int t = dir ? 511 : 0;
        pgR = preG[((size_t)t * 16 + col) * 32 + eb];
        pgU = preG[((size_t)t * 16 + 8 + col) * 32 + eb];
        pcA = preC[((size_t)t * 8 + col) * 32 + eb];
    }

    for (int s = 0; s < 512; ++s) {
        const int t  = dir ? (511 - s) : s;
        const int tn = dir ? (510 - s) : (s + 1);

        // ---- wait for all h updates of previous step ----
        wait_for(cB, (unsigned)s * 64u);

        // ---- load h slice + hold into registers ----
        ull hh[32];
#pragma unroll
        for (int q = 0; q < 32; ++q) {
            float lo = hT[(k0 + 2 * q) * 32 + b];
            float hi = hT[(k0 + 2 * q + 1) * 32 + b];
            PACK2(hh[q], lo, hi);
        }
        float hold = hT[(j0 + col) * 32 + eb];

        // ---- r GEMM ----
        {
            ull acc[8];
#pragma unroll
            for (int jj = 0; jj < 8; ++jj) acc[jj] = 0ull;
#pragma unroll
            for (int q2 = 0; q2 < 16; ++q2) {
#pragma unroll
                for (int jj = 0; jj < 8; ++jj) {
                    ulonglong2 ww = *(const ulonglong2*)&Wr_s[jj * 516 + k0 + q2 * 4];
                    FMA2(acc[jj], hh[2 * q2],     ww.x);
                    FMA2(acc[jj], hh[2 * q2 + 1], ww.y);
                }
            }
#pragma unroll
            for (int jj = 0; jj < 8; ++jj) {
                float2 v = unpk(acc[jj]);
                red[warp * 264 + jj * 33 + b] = v.x + v.y;
            }
        }
        __syncthreads();
        // reduce + sigmoid -> ruT
        {
            float v = pgR;
#pragma unroll
            for (int q = 0; q < 8; ++q) v += red[q * 264 + col * 33 + eb];
            ruT[(j0 + col) * 32 + eb] = 1.f / (1.f + __expf(-v));
        }
        arrive(cA);   // r published (includes syncthreads)

        // ---- u GEMM (hides barrier A round-trip); u stays in registers ----
        float ureg;
        {
            ull acc[8];
#pragma unroll
            for (int jj = 0; jj < 8; ++jj) acc[jj] = 0ull;
#pragma unroll
            for (int q2 = 0; q2 < 16; ++q2) {
#pragma unroll
                for (int jj = 0; jj < 8; ++jj) {
                    ulonglong2 ww = *(const ulonglong2*)&Wu_s[jj * 516 + k0 + q2 * 4];
                    FMA2(acc[jj], hh[2 * q2],     ww.x);
                    FMA2(acc[jj], hh[2 * q2 + 1], ww.y);
                }
            }
#pragma unroll
            for (int jj = 0; jj < 8; ++jj) {
                float2 v = unpk(acc[jj]);
                red[warp * 264 + jj * 33 + b] = v.x + v.y;
            }
        }
        __syncthreads();
        {
            float v = pgU;
#pragma unroll
            for (int q = 0; q < 8; ++q) v += red[q * 264 + col * 33 + eb];
            ureg = 1.f / (1.f + __expf(-v));
        }
        // prefetch next-step gate pre while waiting
        if (s < 511) {
            pgR = preG[((size_t)tn * 16 + col) * 32 + eb];
            pgU = preG[((size_t)tn * 16 + 8 + col) * 32 + eb];
        }

        // ---- wait for all r, then candidate ----
        wait_for(cA, (unsigned)(s + 1) * 64u);
        {
            // rh in registers
#pragma unroll
            for (int q = 0; q < 32; ++q) {
                float lo = ruT[(k0 + 2 * q) * 32 + b];
                float hi = ruT[(k0 + 2 * q + 1) * 32 + b];
                ull rp;
                PACK2(rp, lo, hi);
                MUL2(hh[q], hh[q], rp);
            }
            ull acc[8];
#pragma unroll
            for (int jj = 0; jj < 8; ++jj) acc[jj] = 0ull;
#pragma unroll
            for (int q2 = 0; q2 < 16; ++q2) {
#pragma unroll
                for (int jj = 0; jj < 8; ++jj) {
                    ulonglong2 ww = *(const ulonglong2*)&Wc_s[jj * 516 + k0 + q2 * 4];
                    FMA2(acc[jj], hh[2 * q2],     ww.x);
                    FMA2(acc[jj], hh[2 * q2 + 1], ww.y);
                }
            }
#pragma unroll
            for (int jj = 0; jj < 8; ++jj) {
                float2 v = unpk(acc[jj]);
                red[warp * 264 + jj * 33 + b] = v.x + v.y;
            }
        }
        __syncthreads();
        // ---- epilogue: tanh + h update ----
        {
            float v = pcA;
#pragma unroll
            for (int q = 0; q < 8; ++q) v += red[q * 264 + col * 33 + eb];
            float ct = tanhf(v);
            float hn = ureg * hold + (1.f - ureg) * ct;
            hT[(j0 + col) * 32 + eb] = hn;
            outp[(size_t)(t * 32 + eb) * 512 + j0 + col] = hn;
        }
        if (s < 511)
            pcA = preC[((size_t)tn * 8 + col) * 32 + eb];
        arrive(cB);
    }
}

// ---------------- FC over shifted-context concat + relu + max-pool ----------------
__global__ __launch_bounds__(256, 2) void k_fc(const float* __restrict__ fcw,
                                               const float* __restrict__ fcb)
{
    __shared__ __align__(16) float As[16 * 132];
    __shared__ __align__(16) float Bs[16 * 132];
    const int n0 = blockIdx.x * 128;
    const int m0 = blockIdx.y * 128;
    const int tid = threadIdx.x;
    const int tx = tid & 15, ty = tid >> 4;
    ull acc[8][4];
#pragma unroll
    for (int i = 0; i < 8; i++)
#pragma unroll
        for (int j = 0; j < 4; j++) acc[i][j] = 0ull;

    for (int k0 = 0; k0 < 1280; k0 += 16) {
#pragma unroll
        for (int i = 0; i < 2; ++i) {
            int f = tid + i * 256;
            int r = f >> 2, c4 = (f & 3) * 4;
            int m = m0 + r;
            int c = k0 + c4;
            float4 v = make_float4(0.f, 0.f, 0.f, 0.f);
            if (c < 512) {                        // c_left = out_fw[t-1]
                if (m >= 32) v = *(const float4*)&g_outf[(size_t)(m - 32) * 512 + c];
            } else if (c < 768) {                 // x[t]
                v = *(const float4*)&g_xt[(size_t)m * 256 + (c - 512)];
            } else {                              // c_right = out_bw[t+1]
                if (m < 16352) v = *(const float4*)&g_outb[(size_t)(m + 32) * 512 + (c - 768)];
            }
            As[(c4 + 0) * 132 + r] = v.x;
            As[(c4 + 1) * 132 + r] = v.y;
            As[(c4 + 2) * 132 + r] = v.z;
            As[(c4 + 3) * 132 + r] = v.w;
        }
#pragma unroll
        for (int i = 0; i < 2; ++i) {
            int f = tid + i * 256;
            int kk = f >> 5, n4 = (f & 31) * 4;
            *(float4*)&Bs[kk * 132 + n4] = *(const float4*)&fcw[(size_t)(k0 + kk) * 512 + n0 + n4];
        }
        __syncthreads();
#pragma unroll
        for (int kk = 0; kk < 16; ++kk) {
            float4 a0 = *(const float4*)&As[kk * 132 + ty * 8];
            float4 a1 = *(const float4*)&As[kk * 132 + ty * 8 + 4];
            ulonglong2 w01 = *(const ulonglong2*)&Bs[kk * 132 + tx * 8];
            ulonglong2 w23 = *(const ulonglong2*)&Bs[kk * 132 + tx * 8 + 4];
            ull ad[8];
            ad[0] = dup2f(a0.x); ad[1] = dup2f(a0.y); ad[2] = dup2f(a0.z); ad[3] = dup2f(a0.w);
            ad[4] = dup2f(a1.x); ad[5] = dup2f(a1.y); ad[6] = dup2f(a1.z); ad[7] = dup2f(a1.w);
#pragma unroll
            for (int i = 0; i < 8; i++) {
                FMA2(acc[i][0], ad[i], w01.x);
                FMA2(acc[i][1], ad[i], w01.y);
                FMA2(acc[i][2], ad[i], w23.x);
                FMA2(acc[i][3], ad[i], w23.y);
            }
        }
        __syncthreads();
    }
    float4 bb0 = *(const float4*)&fcb[n0 + tx * 8];
    float4 bb1 = *(const float4*)&fcb[n0 + tx * 8 + 4];
    float bcol[8] = {bb0.x, bb0.y, bb0.z, bb0.w, bb1.x, bb1.y, bb1.z, bb1.w};
#pragma unroll
    for (int i = 0; i < 8; i++) {
        int m = m0 + ty * 8 + i;
        int bb = m & 31;
        int base = bb * 512 + n0 + tx * 8;
#pragma unroll
        for (int j = 0; j < 4; j++) {
            float2 v = unpk(acc[i][j]);
            float r0 = fmaxf(v.x + bcol[2 * j], 0.f);
            float r1 = fmaxf(v.y + bcol[2 * j + 1], 0.f);
            atomicMax((int*)&g_pool[base + 2 * j + 0], __float_as_int(r0));
            atomicMax((int*)&g_pool[base + 2 * j + 1], __float_as_int(r1));
        }
    }
}

// ---------------- MLP head ----------------
__global__ void k_mlp(const float* __restrict__ mw, const float* __restrict__ mb,
                      float* __restrict__ out)
{
    __shared__ float sp[512];
    int bb = blockIdx.x;
    int tid = threadIdx.x;
    for (int i = tid; i < 512; i += 256) sp[i] = g_pool[bb * 512 + i];
    __syncthreads();
    float acc = mb[tid];
#pragma unroll 8
    for (int h = 0; h < 512; ++h) acc += sp[h] * mw[h * 256 + tid];
    out[bb * 256 + tid] = acc;
}

// ---------------- launch ----------------
extern "C" void kernel_launch(void* const* d_in, const int* in_sizes, int n_in,
                              void* d_out, int out_size)
{
    const float* x    = (const float*)d_in[0];
    const float* fwWg = (const float*)d_in[1];
    const float* fwbg = (const float*)d_in[2];
    const float* fwWc = (const float*)d_in[3];
    const float* fwbc = (const float*)d_in[4];
    const float* bwWg = (const float*)d_in[5];
    const float* bwbg = (const float*)d_in[6];
    const float* bwWc = (const float*)d_in[7];
    const float* bwbc = (const float*)d_in[8];
    const float* fcw  = (const float*)d_in[9];
    const float* fcb  = (const float*)d_in[10];
    const float* mw   = (const float*)d_in[11];
    const float* mb   = (const float*)d_in[12];
    float* out = (float*)d_out;

    cudaFuncSetAttribute(k_recur, cudaFuncAttributeMaxDynamicSharedMemorySize, 57984);

    k_init<<<128, 256>>>();
    k_xcopy<<<4096, 256>>>(x);
    k_gemm_pre<<<dim3(24, 128), 256>>>(x, fwWg, fwbg, fwWc, fwbc, bwWg, bwbg, bwWc, bwbc);
    k_recur<<<128, 256, 57984>>>(fwWg, fwWc, bwWg, bwWc);
    k_fc<<<dim3(4, 128), 256>>>(fcw, fcb);
    k_mlp<<<32, 256>>>(mw, mb, out);
}

// round 6
// speedup vs baseline: 1.2838x; 1.0024x over previous
#include <cuda_runtime.h>
#include <math.h>

typedef unsigned long long ull;

#define FMA2(d, a, b) asm("fma.rn.f32x2 %0, %1, %2, %0;" : "+l"(d) : "l"(a), "l"(b))
#define MUL2(d, a, b) asm("mul.rn.f32x2 %0, %1, %2;" : "=l"(d) : "l"(a), "l"(b))
#define PACK2(d, lo, hi) asm("mov.b64 %0, {%1, %2};" : "=l"(d) : "f"(lo), "f"(hi))

__device__ __forceinline__ ull dup2f(float a) {
    ull r; asm("mov.b64 %0, {%1, %1};" : "=l"(r) : "f"(a)); return r;
}
__device__ __forceinline__ float2 unpk(ull v) {
    float2 f; asm("mov.b64 {%0, %1}, %2;" : "=f"(f.x), "=f"(f.y) : "l"(v)); return f;
}

// ---------------- device scratch ----------------
// gate pre [dir*64+c64][t][16][32] : sub 0..7 = r cols (c64*8+j), 8..15 = u cols
__device__ float g_preG[(size_t)2 * 64 * 512 * 16 * 32];
__device__ float g_preC[(size_t)2 * 64 * 512 * 8 * 32];
__device__ float g_xt [(size_t)512 * 32 * 256];  // x: [t][b][c]
__device__ float g_outf[(size_t)512 * 32 * 512]; // fw hidden [t][b][h]
__device__ float g_outb[(size_t)512 * 32 * 512]; // bw hidden [t][b][h]
__device__ float g_hT [2 * 512 * 32];            // h transposed [dir][col][b]
__device__ float g_ruT[2 * 512 * 32];            // sigmoided r only [dir][col][b]
__device__ float g_pool[32 * 512];
// distributed flags: one padded word per CTA (128B apart), per direction/phase
__device__ unsigned g_flagA[2][64 * 32];
__device__ unsigned g_flagB[2][64 * 32];

// ---------------- init ----------------
__global__ void k_init() {
    int i = blockIdx.x * blockDim.x + threadIdx.x;
    if (i < 2 * 512 * 32) g_hT[i] = 0.f;
    if (i < 32 * 512)     g_pool[i] = 0.f;
    if (i < 2 * 64 * 32) { g_flagA[0][i] = 0u; g_flagB[0][i] = 0u; }
}

// ---------------- x -> [t][b][c] copy ----------------
__global__ void k_xcopy(const float* __restrict__ x) {
    int idx = blockIdx.x * blockDim.x + threadIdx.x;  // float4 id
    if (idx < 32 * 512 * 64) {
        int row = idx >> 6, c4 = idx & 63;            // row = b*512 + t
        int b = row >> 9, t = row & 511;
        ((float4*)g_xt)[(size_t)(t * 32 + b) * 64 + c4] = ((const float4*)x)[idx];
    }
}

// ---------------- GEMM1: x-part projections (M=16384,K=256,N=3072), double-buffered ----------------
__global__ __launch_bounds__(256, 2) void k_gemm_pre(
    const float* __restrict__ x,
    const float* __restrict__ fwWg, const float* __restrict__ fwbg,
    const float* __restrict__ fwWc, const float* __restrict__ fwbc,
    const float* __restrict__ bwWg, const float* __restrict__ bwbg,
    const float* __restrict__ bwWc, const float* __restrict__ bwbc)
{
    __shared__ __align__(16) float As[2][16 * 132];
    __shared__ __align__(16) float Bs[2][16 * 132];
    const int n0 = blockIdx.x * 128;
    const int m0 = blockIdx.y * 128;
    const float* W; const float* bias; int ld, nrel, dir, isC;
    if (n0 < 1024)      { W = fwWg; bias = fwbg; ld = 1024; nrel = n0;        dir = 0; isC = 0; }
    else if (n0 < 1536) { W = fwWc; bias = fwbc; ld = 512;  nrel = n0 - 1024; dir = 0; isC = 1; }
    else if (n0 < 2560) { W = bwWg; bias = bwbg; ld = 1024; nrel = n0 - 1536; dir = 1; isC = 0; }
    else                { W = bwWc; bias = bwbc; ld = 512;  nrel = n0 - 2560; dir = 1; isC = 1; }
    const int tid = threadIdx.x;
    const int tx = tid & 15, ty = tid >> 4;
    // loader indices
    const int ar0 = tid >> 2, ac0 = (tid & 3) * 4;            // A: row, k within slab (i=0)
    const int ar1 = (tid + 256) >> 2, ac1 = (tid & 3) * 4;
    const int bk0 = tid >> 5, bn0 = (tid & 31) * 4;           // B: k, n within slab
    const int bk1 = (tid + 256) >> 5;

    ull acc[8][4];
#pragma unroll
    for (int i = 0; i < 8; i++)
#pragma unroll
        for (int j = 0; j < 4; j++) acc[i][j] = 0ull;

    float4 pa0, pa1, pb0, pb1;
    pa0 = *(const float4*)&x[(size_t)(m0 + ar0) * 256 + ac0];
    pa1 = *(const float4*)&x[(size_t)(m0 + ar1) * 256 + ac1];
    pb0 = *(const float4*)&W[(size_t)bk0 * ld + nrel + bn0];
    pb1 = *(const float4*)&W[(size_t)bk1 * ld + nrel + bn0];
    {
        As[0][(ac0 + 0) * 132 + ar0] = pa0.x; As[0][(ac0 + 1) * 132 + ar0] = pa0.y;
        As[0][(ac0 + 2) * 132 + ar0] = pa0.z; As[0][(ac0 + 3) * 132 + ar0] = pa0.w;
        As[0][(ac1 + 0) * 132 + ar1] = pa1.x; As[0][(ac1 + 1) * 132 + ar1] = pa1.y;
        As[0][(ac1 + 2) * 132 + ar1] = pa1.z; As[0][(ac1 + 3) * 132 + ar1] = pa1.w;
        *(float4*)&Bs[0][bk0 * 132 + bn0] = pb0;
        *(float4*)&Bs[0][bk1 * 132 + bn0] = pb1;
    }
    __syncthreads();
    int p = 0;
    for (int slab = 0; slab < 16; ++slab) {
        if (slab < 15) {
            int k0 = (slab + 1) * 16;
            pa0 = *(const float4*)&x[(size_t)(m0 + ar0) * 256 + k0 + ac0];
            pa1 = *(const float4*)&x[(size_t)(m0 + ar1) * 256 + k0 + ac1];
            pb0 = *(const float4*)&W[(size_t)(k0 + bk0) * ld + nrel + bn0];
            pb1 = *(const float4*)&W[(size_t)(k0 + bk1) * ld + nrel + bn0];
        }
#pragma unroll
        for (int kk = 0; kk < 16; ++kk) {
            float4 a0 = *(const float4*)&As[p][kk * 132 + ty * 8];
            float4 a1 = *(const float4*)&As[p][kk * 132 + ty * 8 + 4];
            ulonglong2 w01 = *(const ulonglong2*)&Bs[p][kk * 132 + tx * 8];
            ulonglong2 w23 = *(const ulonglong2*)&Bs[p][kk * 132 + tx * 8 + 4];
            ull ad[8];
            ad[0] = dup2f(a0.x); ad[1] = dup2f(a0.y); ad[2] = dup2f(a0.z); ad[3] = dup2f(a0.w);
            ad[4] = dup2f(a1.x); ad[5] = dup2f(a1.y); ad[6] = dup2f(a1.z); ad[7] = dup2f(a1.w);
#pragma unroll
            for (int i = 0; i < 8; i++) {
                FMA2(acc[i][0], ad[i], w01.x);
                FMA2(acc[i][1], ad[i], w01.y);
                FMA2(acc[i][2], ad[i], w23.x);
                FMA2(acc[i][3], ad[i], w23.y);
            }
        }
        if (slab < 15) {
            int q = p ^ 1;
            As[q][(ac0 + 0) * 132 + ar0] = pa0.x; As[q][(ac0 + 1) * 132 + ar0] = pa0.y;
            As[q][(ac0 + 2) * 132 + ar0] = pa0.z; As[q][(ac0 + 3) * 132 + ar0] = pa0.w;
            As[q][(ac1 + 0) * 132 + ar1] = pa1.x; As[q][(ac1 + 1) * 132 + ar1] = pa1.y;
            As[q][(ac1 + 2) * 132 + ar1] = pa1.z; As[q][(ac1 + 3) * 132 + ar1] = pa1.w;
            *(float4*)&Bs[q][bk0 * 132 + bn0] = pb0;
            *(float4*)&Bs[q][bk1 * 132 + bn0] = pb1;
            __syncthreads();
            p = q;
        }
    }
    float4 bb0 = *(const float4*)&bias[nrel + tx * 8];
    float4 bb1 = *(const float4*)&bias[nrel + tx * 8 + 4];
    float bcol[8] = {bb0.x, bb0.y, bb0.z, bb0.w, bb1.x, bb1.y, bb1.z, bb1.w};
    const int cbase = nrel + tx * 8;
#pragma unroll
    for (int i = 0; i < 8; i++) {
        int m = m0 + ty * 8 + i;
        int t = m & 511, bb = m >> 9;
        float vals[8];
#pragma unroll
        for (int j = 0; j < 4; j++) {
            float2 v = unpk(acc[i][j]);
            vals[2 * j] = v.x + bcol[2 * j];
            vals[2 * j + 1] = v.y + bcol[2 * j + 1];
        }
        if (!isC) {
            int c, sub0;
            if (cbase < 512) { c = cbase >> 3; sub0 = 0; }
            else             { c = (cbase - 512) >> 3; sub0 = 8; }
            float* dst = &g_preG[(((size_t)(dir * 64 + c) * 512 + t) * 16 + sub0) * 32 + bb];
#pragma unroll
            for (int cc = 0; cc < 8; ++cc) dst[cc * 32] = vals[cc];
        } else {
            int c = cbase >> 3;
            float* dst = &g_preC[(((size_t)(dir * 64 + c) * 512 + t) * 8) * 32 + bb];
#pragma unroll
            for (int cc = 0; cc < 8; ++cc) dst[cc * 32] = vals[cc];
        }
    }
}

// ---------------- distributed-flag barrier ----------------
__device__ __forceinline__ void arrive_flag(unsigned* flag, int c64, unsigned val) {
    __syncthreads();
    if (threadIdx.x == 0) {
        __threadfence();
        *(volatile unsigned*)&flag[c64 * 32] = val;
    }
}
__device__ __forceinline__ void wait_flag(unsigned* flag, unsigned target) {
    if (threadIdx.x < 64) {
        volatile unsigned* f = (volatile unsigned*)&flag[threadIdx.x * 32];
        while (*f < target) { }
    }
    if (threadIdx.x == 0) __threadfence();
    __syncthreads();
}

// ---------------- persistent bidirectional GRU ----------------
// 128 CTAs x 512 threads: dir = cta>>6, c64 = cta&63. CTA owns cols [c64*8, c64*8+8).
// 16-way k-split (32 h per thread). u stays in registers. Flags replace atomics.
__global__ __launch_bounds__(512, 1) void k_recur(
    const float* __restrict__ fwWg, const float* __restrict__ fwWc,
    const float* __restrict__ bwWg, const float* __restrict__ bwWc)
{
    extern __shared__ float sm[];
    float* Wr_s = sm;             // 8 x 516
    float* Wu_s = sm + 4128;      // 8 x 516
    float* Wc_s = sm + 8256;      // 8 x 516
    float* red  = sm + 12384;     // 16 warps x 8 cols x 33

    const int tid = threadIdx.x;
    const int cta = blockIdx.x;
    const int dir = cta >> 6;
    const int c64 = cta & 63;
    const int j0 = c64 * 8;
    const float* Wg = dir ? bwWg : fwWg;
    const float* Wc = dir ? bwWc : fwWc;

    for (int idx = tid; idx < 8 * 512; idx += 512) {
        int jj = idx & 7, k = idx >> 3;
        Wr_s[jj * 516 + k] = Wg[(size_t)(256 + k) * 1024 + j0 + jj];
        Wu_s[jj * 516 + k] = Wg[(size_t)(256 + k) * 1024 + 512 + j0 + jj];
        Wc_s[jj * 516 + k] = Wc[(size_t)(256 + k) * 512 + j0 + jj];
    }
    __syncthreads();

    const int warp = tid >> 5;
    const int b = tid & 31;
    const int k0 = warp * 32;        // 16 warps x 32 k
    const int col = (tid >> 5) & 7;  // epilogue/reduce mapping (tid<256)
    const int eb = tid & 31;

    const float* preG = g_preG + (size_t)(dir * 64 + c64) * 512 * 16 * 32;
    const float* preC = g_preC + (size_t)(dir * 64 + c64) * 512 * 8 * 32;
    float* ruT = g_ruT + (size_t)dir * 512 * 32;
    float* hT  = g_hT  + (size_t)dir * 512 * 32;
    float* outp = dir ? g_outb : g_outf;
    unsigned* fA = g_flagA[dir];
    unsigned* fB = g_flagB[dir];

    // prefetch step-0 x-projections
    float pgR = 0.f, pgU = 0.f, pcA = 0.f;
    if (tid < 256) {
        int t = dir ? 511 : 0;
        pgR = preG[((size_t)t * 16 + col) * 32 + eb];
        pgU = preG[((size_t)t * 16 + 8 + col) * 32 + eb];
        pcA = preC[((size_t)t * 8 + col) * 32 + eb];
    }

    for (int s = 0; s < 512; ++s) {
        const int t  = dir ? (511 - s) : s;
        const int tn = dir ? (510 - s) : (s + 1);

        // ---- wait for all h updates of previous step ----
        wait_flag(fB, (unsigned)s);

        // ---- load h slice + hold into registers ----
        ull hh[16];
#pragma unroll
        for (int q = 0; q < 16; ++q) {
            float lo = hT[(k0 + 2 * q) * 32 + b];
            float hi = hT[(k0 + 2 * q + 1) * 32 + b];
            PACK2(hh[q], lo, hi);
        }
        float hold = (tid < 256) ? hT[(j0 + col) * 32 + eb] : 0.f;

        // ---- r GEMM ----
        {
            ull acc[8];
#pragma unroll
            for (int jj = 0; jj < 8; ++jj) acc[jj] = 0ull;
#pragma unroll
            for (int q2 = 0; q2 < 8; ++q2) {
#pragma unroll
                for (int jj = 0; jj < 8; ++jj) {
                    ulonglong2 ww = *(const ulonglong2*)&Wr_s[jj * 516 + k0 + q2 * 4];
                    FMA2(acc[jj], hh[2 * q2],     ww.x);
                    FMA2(acc[jj], hh[2 * q2 + 1], ww.y);
                }
            }
#pragma unroll
            for (int jj = 0; jj < 8; ++jj) {
                float2 v = unpk(acc[jj]);
                red[warp * 264 + jj * 33 + b] = v.x + v.y;
            }
        }
        __syncthreads();
        if (tid < 256) {
            float v = pgR;
#pragma unroll
            for (int q = 0; q < 16; ++q) v += red[q * 264 + col * 33 + eb];
            ruT[(j0 + col) * 32 + eb] = 1.f / (1.f + __expf(-v));
        }
        arrive_flag(fA, c64, (unsigned)(s + 1));   // r published

        // ---- u GEMM (hides barrier A propagation); u stays in registers ----
        float ureg = 0.f;
        {
            ull acc[8];
#pragma unroll
            for (int jj = 0; jj < 8; ++jj) acc[jj] = 0ull;
#pragma unroll
            for (int q2 = 0; q2 < 8; ++q2) {
#pragma unroll
                for (int jj = 0; jj < 8; ++jj) {
                    ulonglong2 ww = *(const ulonglong2*)&Wu_s[jj * 516 + k0 + q2 * 4];
                    FMA2(acc[jj], hh[2 * q2],     ww.x);
                    FMA2(acc[jj], hh[2 * q2 + 1], ww.y);
                }
            }
#pragma unroll
            for (int jj = 0; jj < 8; ++jj) {
                float2 v = unpk(acc[jj]);
                red[warp * 264 + jj * 33 + b] = v.x + v.y;
            }
        }
        __syncthreads();
        if (tid < 256) {
            float v = pgU;
#pragma unroll
            for (int q = 0; q < 16; ++q) v += red[q * 264 + col * 33 + eb];
            ureg = 1.f / (1.f + __expf(-v));
            if (s < 511) {
                pgR = preG[((size_t)tn * 16 + col) * 32 + eb];
                pgU = preG[((size_t)tn * 16 + 8 + col) * 32 + eb];
            }
        }

        // ---- wait for all r, then candidate ----
        wait_flag(fA, (unsigned)(s + 1));
        {
#pragma unroll
            for (int q = 0; q < 16; ++q) {
                float lo = ruT[(k0 + 2 * q) * 32 + b];
                float hi = ruT[(k0 + 2 * q + 1) * 32 + b];
                ull rp;
                PACK2(rp, lo, hi);
                MUL2(hh[q], hh[q], rp);
            }
            ull acc[8];
#pragma unroll
            for (int jj = 0; jj < 8; ++jj) acc[jj] = 0ull;
#pragma unroll
            for (int q2 = 0; q2 < 8; ++q2) {
#pragma unroll
                for (int jj = 0; jj < 8; ++jj) {
                    ulonglong2 ww = *(const ulonglong2*)&Wc_s[jj * 516 + k0 + q2 * 4];
                    FMA2(acc[jj], hh[2 * q2],     ww.x);
                    FMA2(acc[jj], hh[2 * q2 + 1], ww.y);
                }
            }
#pragma unroll
            for (int jj = 0; jj < 8; ++jj) {
                float2 v = unpk(acc[jj]);
                red[warp * 264 + jj * 33 + b] = v.x + v.y;
            }
        }
        __syncthreads();
        // ---- epilogue: tanh + h update ----
        if (tid < 256) {
            float v = pcA;
#pragma unroll
            for (int q = 0; q < 16; ++q) v += red[q * 264 + col * 33 + eb];
            float ct = tanhf(v);
            float hn = ureg * hold + (1.f - ureg) * ct;
            hT[(j0 + col) * 32 + eb] = hn;
            outp[(size_t)(t * 32 + eb) * 512 + j0 + col] = hn;
            if (s < 511)
                pcA = preC[((size_t)tn * 8 + col) * 32 + eb];
        }
        arrive_flag(fB, c64, (unsigned)(s + 1));
    }
}

// ---------------- FC over shifted-context concat + relu + max-pool, double-buffered ----------------
__global__ __launch_bounds__(256, 2) void k_fc(const float* __restrict__ fcw,
                                               const float* __restrict__ fcb)
{
    __shared__ __align__(16) float As[2][16 * 132];
    __shared__ __align__(16) float Bs[2][16 * 132];
    const int n0 = blockIdx.x * 128;
    const int m0 = blockIdx.y * 128;
    const int tid = threadIdx.x;
    const int tx = tid & 15, ty = tid >> 4;
    const int ar0 = tid >> 2, ac0 = (tid & 3) * 4;
    const int ar1 = (tid + 256) >> 2;
    const int bk0 = tid >> 5, bn0 = (tid & 31) * 4;
    const int bk1 = (tid + 256) >> 5;

    ull acc[8][4];
#pragma unroll
    for (int i = 0; i < 8; i++)
#pragma unroll
        for (int j = 0; j < 4; j++) acc[i][j] = 0ull;

    auto gather = [&](int m, int c) -> float4 {
        float4 v = make_float4(0.f, 0.f, 0.f, 0.f);
        if (c < 512) {
            if (m >= 32) v = *(const float4*)&g_outf[(size_t)(m - 32) * 512 + c];
        } else if (c < 768) {
            v = *(const float4*)&g_xt[(size_t)m * 256 + (c - 512)];
        } else {
            if (m < 16352) v = *(const float4*)&g_outb[(size_t)(m + 32) * 512 + (c - 768)];
        }
        return v;
    };

    float4 pa0, pa1, pb0, pb1;
    pa0 = gather(m0 + ar0, ac0);
    pa1 = gather(m0 + ar1, ac0);
    pb0 = *(const float4*)&fcw[(size_t)bk0 * 512 + n0 + bn0];
    pb1 = *(const float4*)&fcw[(size_t)bk1 * 512 + n0 + bn0];
    {
        As[0][(ac0 + 0) * 132 + ar0] = pa0.x; As[0][(ac0 + 1) * 132 + ar0] = pa0.y;
        As[0][(ac0 + 2) * 132 + ar0] = pa0.z; As[0][(ac0 + 3) * 132 + ar0] = pa0.w;
        As[0][(ac0 + 0) * 132 + ar1] = pa1.x; As[0][(ac0 + 1) * 132 + ar1] = pa1.y;
        As[0][(ac0 + 2) * 132 + ar1] = pa1.z; As[0][(ac0 + 3) * 132 + ar1] = pa1.w;
        *(float4*)&Bs[0][bk0 * 132 + bn0] = pb0;
        *(float4*)&Bs[0][bk1 * 132 + bn0] = pb1;
    }
    __syncthreads();
    int p = 0;
    for (int slab = 0; slab < 80; ++slab) {
        if (slab < 79) {
            int k0 = (slab + 1) * 16;
            pa0 = gather(m0 + ar0, k0 + ac0);
            pa1 = gather(m0 + ar1, k0 + ac0);
            pb0 = *(const float4*)&fcw[(size_t)(k0 + bk0) * 512 + n0 + bn0];
            pb1 = *(const float4*)&fcw[(size_t)(k0 + bk1) * 512 + n0 + bn0];
        }
#pragma unroll
        for (int kk = 0; kk < 16; ++kk) {
            float4 a0 = *(const float4*)&As[p][kk * 132 + ty * 8];
            float4 a1 = *(const float4*)&As[p][kk * 132 + ty * 8 + 4];
            ulonglong2 w01 = *(const ulonglong2*)&Bs[p][kk * 132 + tx * 8];
            ulonglong2 w23 = *(const ulonglong2*)&Bs[p][kk * 132 + tx * 8 + 4];
            ull ad[8];
            ad[0] = dup2f(a0.x); ad[1] = dup2f(a0.y); ad[2] = dup2f(a0.z); ad[3] = dup2f(a0.w);
            ad[4] = dup2f(a1.x); ad[5] = dup2f(a1.y); ad[6] = dup2f(a1.z); ad[7] = dup2f(a1.w);
#pragma unroll
            for (int i = 0; i < 8; i++) {
                FMA2(acc[i][0], ad[i], w01.x);
                FMA2(acc[i][1], ad[i], w01.y);
                FMA2(acc[i][2], ad[i], w23.x);
                FMA2(acc[i][3], ad[i], w23.y);
            }
        }
        if (slab < 79) {
            int q = p ^ 1;
            As[q][(ac0 + 0) * 132 + ar0] = pa0.x; As[q][(ac0 + 1) * 132 + ar0] = pa0.y;
            As[q][(ac0 + 2) * 132 + ar0] = pa0.z; As[q][(ac0 + 3) * 132 + ar0] = pa0.w;
            As[q][(ac0 + 0) * 132 + ar1] = pa1.x; As[q][(ac0 + 1) * 132 + ar1] = pa1.y;
            As[q][(ac0 + 2) * 132 + ar1] = pa1.z; As[q][(ac0 + 3) * 132 + ar1] = pa1.w;
            *(float4*)&Bs[q][bk0 * 132 + bn0] = pb0;
            *(float4*)&Bs[q][bk1 * 132 + bn0] = pb1;
            __syncthreads();
            p = q;
        }
    }
    float4 bb0 = *(const float4*)&fcb[n0 + tx * 8];
    float4 bb1 = *(const float4*)&fcb[n0 + tx * 8 + 4];
    float bcol[8] = {bb0.x, bb0.y, bb0.z, bb0.w, bb1.x, bb1.y, bb1.z, bb1.w};
#pragma unroll
    for (int i = 0; i < 8; i++) {
        int m = m0 + ty * 8 + i;
        int bb = m & 31;
        int base = bb * 512 + n0 + tx * 8;
#pragma unroll
        for (int j = 0; j < 4; j++) {
            float2 v = unpk(acc[i][j]);
            float r0 = fmaxf(v.x + bcol[2 * j], 0.f);
            float r1 = fmaxf(v.y + bcol[2 * j + 1], 0.f);
            atomicMax((int*)&g_pool[base + 2 * j + 0], __float_as_int(r0));
            atomicMax((int*)&g_pool[base + 2 * j + 1], __float_as_int(r1));
        }
    }
}

// ---------------- MLP head ----------------
__global__ void k_mlp(const float* __restrict__ mw, const float* __restrict__ mb,
                      float* __restrict__ out)
{
    __shared__ float sp[512];
    int bb = blockIdx.x;
    int tid = threadIdx.x;
    for (int i = tid; i < 512; i += 256) sp[i] = g_pool[bb * 512 + i];
    __syncthreads();
    float acc = mb[tid];
#pragma unroll 8
    for (int h = 0; h < 512; ++h) acc += sp[h] * mw[h * 256 + tid];
    out[bb * 256 + tid] = acc;
}

// ---------------- launch ----------------
extern "C" void kernel_launch(void* const* d_in, const int* in_sizes, int n_in,
                              void* d_out, int out_size)
{
    const float* x    = (const float*)d_in[0];
    const float* fwWg = (const float*)d_in[1];
    const float* fwbg = (const float*)d_in[2];
    const float* fwWc = (const float*)d_in[3];
    const float* fwbc = (const float*)d_in[4];
    const float* bwWg = (const float*)d_in[5];
    const float* bwbg = (const float*)d_in[6];
    const float* bwWc = (const float*)d_in[7];
    const float* bwbc = (const float*)d_in[8];
    const float* fcw  = (const float*)d_in[9];
    const float* fcb  = (const float*)d_in[10];
    const float* mw   = (const float*)d_in[11];
    const float* mb   = (const float*)d_in[12];
    float* out = (float*)d_out;

    cudaFuncSetAttribute(k_recur, cudaFuncAttributeMaxDynamicSharedMemorySize, 66432);

    k_init<<<128, 256>>>();
    k_xcopy<<<4096, 256>>>(x);
    k_gemm_pre<<<dim3(24, 128), 256>>>(x, fwWg, fwbg, fwWc, fwbc, bwWg, bwbg, bwWc, bwbc);
    k_recur<<<128, 512, 66432>>>(fwWg, fwWc, bwWg, bwWc);
    k_fc<<<dim3(4, 128), 256>>>(fcw, fcb);
    k_mlp<<<32, 256>>>(mw, mb, out);
}